// round 1
// baseline (speedup 1.0000x reference)
#include <cuda_runtime.h>

#define N_NODES 50000
#define N_EDGES 1000000
#define IN_DIM  256
#define N_ETYPE 1000
#define L1_DIM  16

// Scratch: per-node MLP outputs (relu(z@w1_l1), relu(z@w2_l1)), 3.2 MB each.
__device__ __align__(16) float g_h1[N_NODES * L1_DIM];
__device__ __align__(16) float g_h2[N_NODES * L1_DIM];
// Index-dtype flag: 1 if edge_index/edge_type are int64, 0 if int32.
__device__ int g_is64;

// ---------------------------------------------------------------------------
// Packed f32x2 FMA (Blackwell FFMA2, PTX-only path)
// ---------------------------------------------------------------------------
__device__ __forceinline__ unsigned long long ffma2(unsigned long long a,
                                                    unsigned long long b,
                                                    unsigned long long c) {
    unsigned long long d;
    asm("fma.rn.f32x2 %0, %1, %2, %3;" : "=l"(d) : "l"(a), "l"(b), "l"(c));
    return d;
}

__device__ __forceinline__ float f2_sum(unsigned long long a) {
    unsigned int lo, hi;
    asm("mov.b64 {%0, %1}, %2;" : "=r"(lo), "=r"(hi) : "l"(a));
    return __uint_as_float(lo) + __uint_as_float(hi);
}

// ---------------------------------------------------------------------------
// Detect whether edge_index was materialized as int64 or int32.
// Values are in [0, 50000) and non-negative, so if int64, every odd 32-bit
// word (the high half) is zero. If int32, odd words are uniform random edge
// indices — P(32 consecutive == 0) ~ 0.
// ---------------------------------------------------------------------------
__global__ void detect_kernel(const unsigned int* __restrict__ w) {
    unsigned int v = w[2 * threadIdx.x + 1];
    unsigned int b = __ballot_sync(0xffffffffu, v == 0u);
    if (threadIdx.x == 0) g_is64 = (b == 0xffffffffu) ? 1 : 0;
}

// ---------------------------------------------------------------------------
// Per-node MLP: h1[n] = relu(z[n] @ w1_l1), h2[n] = relu(z[n] @ w2_l1).
// 256 threads/block, 128 nodes/block; thread pair (m=0 -> w1, m=1 -> w2).
// Weights transposed into shared: sw[m][j][k], matrix stride padded by +8
// floats so the two per-warp broadcast addresses hit disjoint bank groups.
// Inner loop uses fma.rn.f32x2: acc[j] packs (even-k, odd-k) partial sums.
// ---------------------------------------------------------------------------
#define WS_STRIDE 4104   // 16*256 + 8 floats

__global__ __launch_bounds__(256) void node_mlp_kernel(
    const float* __restrict__ z,
    const float* __restrict__ w1,   // [256][16] row-major
    const float* __restrict__ w2)   // [256][16] row-major
{
    __shared__ __align__(16) float sw[2 * WS_STRIDE];

    for (int idx = threadIdx.x; idx < IN_DIM * L1_DIM; idx += 256) {
        int k = idx >> 4;
        int j = idx & 15;
        sw[j * IN_DIM + k]             = w1[idx];
        sw[WS_STRIDE + j * IN_DIM + k] = w2[idx];
    }
    __syncthreads();

    int node = blockIdx.x * 128 + (threadIdx.x >> 1);
    int m    = threadIdx.x & 1;
    if (node >= N_NODES) return;

    const ulonglong2* zr  = (const ulonglong2*)(z + (size_t)node * IN_DIM);
    const ulonglong2* wsr = (const ulonglong2*)(sw + m * WS_STRIDE);

    unsigned long long acc[16];
#pragma unroll
    for (int j = 0; j < 16; j++) acc[j] = 0ull;   // packed (0.f, 0.f)

#pragma unroll 4
    for (int k4 = 0; k4 < IN_DIM / 4; k4++) {
        ulonglong2 zq = zr[k4];                    // (z[4k],z[4k+1]) , (z[4k+2],z[4k+3])
#pragma unroll
        for (int j = 0; j < 16; j++) {
            ulonglong2 wq = wsr[j * (IN_DIM / 4) + k4];
            acc[j] = ffma2(zq.x, wq.x, acc[j]);
            acc[j] = ffma2(zq.y, wq.y, acc[j]);
        }
    }

    float* dst = (m == 0 ? g_h1 : g_h2) + (size_t)node * L1_DIM;
    float4* d4 = (float4*)dst;
#pragma unroll
    for (int q = 0; q < 4; q++) {
        float4 v;
        v.x = fmaxf(f2_sum(acc[4 * q + 0]), 0.f);
        v.y = fmaxf(f2_sum(acc[4 * q + 1]), 0.f);
        v.z = fmaxf(f2_sum(acc[4 * q + 2]), 0.f);
        v.w = fmaxf(f2_sum(acc[4 * q + 3]), 0.f);
        d4[q] = v;
    }
}

// ---------------------------------------------------------------------------
// Per-edge: out[e] = sigmoid( dot(h1[src], w1_l2[ty]) + dot(h2[dst], w2_l2[ty]) )
// One thread per edge; 64 B gathers from the L2-resident h tables, 64 B from
// the L1-resident w_l2 tables, float4-vectorized.
// ---------------------------------------------------------------------------
__global__ __launch_bounds__(256) void edge_kernel(
    const void*  __restrict__ ei,
    const void*  __restrict__ et,
    const float* __restrict__ w1l2,   // [1000][16]
    const float* __restrict__ w2l2,   // [1000][16]
    float*       __restrict__ out)
{
    int e = blockIdx.x * 256 + threadIdx.x;
    if (e >= N_EDGES) return;

    int src, dst, ty;
    if (g_is64) {
        const long long* p = (const long long*)ei;
        src = (int)p[e];
        dst = (int)p[N_EDGES + e];
        ty  = (int)((const long long*)et)[e];
    } else {
        const int* p = (const int*)ei;
        src = p[e];
        dst = p[N_EDGES + e];
        ty  = ((const int*)et)[e];
    }

    const float4* a  = (const float4*)(g_h1 + (size_t)src * L1_DIM);
    const float4* b  = (const float4*)(g_h2 + (size_t)dst * L1_DIM);
    const float4* wa = (const float4*)(w1l2 + (size_t)ty * L1_DIM);
    const float4* wb = (const float4*)(w2l2 + (size_t)ty * L1_DIM);

    float s = 0.f;
#pragma unroll
    for (int q = 0; q < 4; q++) {
        float4 av = a[q], wv = wa[q];
        s = fmaf(av.x, wv.x, s);
        s = fmaf(av.y, wv.y, s);
        s = fmaf(av.z, wv.z, s);
        s = fmaf(av.w, wv.w, s);
        float4 bv = b[q], xv = wb[q];
        s = fmaf(bv.x, xv.x, s);
        s = fmaf(bv.y, xv.y, s);
        s = fmaf(bv.z, xv.z, s);
        s = fmaf(bv.w, xv.w, s);
    }

    out[e] = 1.0f / (1.0f + __expf(-s));
}

// ---------------------------------------------------------------------------
// Launch. Input order (setup_inputs dict):
//   0:z 1:edge_index 2:edge_type 3:w1_l1 4:w1_l2 5:w2_l1 6:w2_l2
// ---------------------------------------------------------------------------
extern "C" void kernel_launch(void* const* d_in, const int* in_sizes, int n_in,
                              void* d_out, int out_size) {
    const float* z    = (const float*)d_in[0];
    const void*  ei   = d_in[1];
    const void*  et   = d_in[2];
    const float* w1l1 = (const float*)d_in[3];
    const float* w1l2 = (const float*)d_in[4];
    const float* w2l1 = (const float*)d_in[5];
    const float* w2l2 = (const float*)d_in[6];
    float* out = (float*)d_out;

    detect_kernel<<<1, 32>>>((const unsigned int*)ei);
    node_mlp_kernel<<<(N_NODES + 127) / 128, 256>>>(z, w1l1, w2l1);
    edge_kernel<<<(N_EDGES + 255) / 256, 256>>>(ei, et, w1l2, w2l2, out);
}

// round 2
// speedup vs baseline: 1.2991x; 1.2991x over previous
#include <cuda_runtime.h>

#define N_NODES 50000
#define N_EDGES 1000000
#define IN_DIM  256
#define N_ETYPE 1000
#define L1_DIM  16

// Scratch: per-node MLP outputs (relu(z@w1_l1), relu(z@w2_l1)), 3.2 MB each.
__device__ __align__(16) float g_h1[N_NODES * L1_DIM];
__device__ __align__(16) float g_h2[N_NODES * L1_DIM];
// Merged L2-layer weights: w12[ty][0:16) = w1_l2[ty], w12[ty][16:32) = w2_l2[ty].
// 128 B per row = exactly one L2 line.
__device__ __align__(128) float g_w12[N_ETYPE * 32];
// Index-dtype flag: 1 if edge_index/edge_type are int64, 0 if int32.
__device__ int g_is64;

// ---------------------------------------------------------------------------
// Packed f32x2 FMA (Blackwell FFMA2, PTX-only path)
// ---------------------------------------------------------------------------
__device__ __forceinline__ unsigned long long ffma2(unsigned long long a,
                                                    unsigned long long b,
                                                    unsigned long long c) {
    unsigned long long d;
    asm("fma.rn.f32x2 %0, %1, %2, %3;" : "=l"(d) : "l"(a), "l"(b), "l"(c));
    return d;
}

__device__ __forceinline__ float f2_sum(unsigned long long a) {
    unsigned int lo, hi;
    asm("mov.b64 {%0, %1}, %2;" : "=r"(lo), "=r"(hi) : "l"(a));
    return __uint_as_float(lo) + __uint_as_float(hi);
}

// ---------------------------------------------------------------------------
// Per-node MLP: h1[n] = relu(z[n] @ w1_l1), h2[n] = relu(z[n] @ w2_l1).
// 256 threads/block, 128 nodes/block; thread pair (m=0 -> w1, m=1 -> w2).
// Also folds in (a) int64-vs-int32 index detection (block 0, warp 0) and
// (b) the w12 merged-table build (first 32000 global threads), removing two
// extra kernel launches.
// ---------------------------------------------------------------------------
#define WS_STRIDE 4104   // 16*256 + 8 floats

__global__ __launch_bounds__(256) void node_mlp_kernel(
    const float* __restrict__ z,
    const float* __restrict__ w1,     // [256][16] row-major
    const float* __restrict__ w2,     // [256][16] row-major
    const float* __restrict__ w1l2,   // [1000][16]
    const float* __restrict__ w2l2,   // [1000][16]
    const unsigned int* __restrict__ ei_words)
{
    __shared__ __align__(16) float sw[2 * WS_STRIDE];

    // (a) dtype detection: edge values < 50000, so int64 => all high words zero.
    if (blockIdx.x == 0 && threadIdx.x < 32) {
        unsigned int v = ei_words[2 * threadIdx.x + 1];
        unsigned int b = __ballot_sync(0xffffffffu, v == 0u);
        if (threadIdx.x == 0) g_is64 = (b == 0xffffffffu) ? 1 : 0;
    }

    // (b) build merged w12 table: 1000 rows x 32 floats.
    {
        int gtid = blockIdx.x * 256 + threadIdx.x;
        if (gtid < N_ETYPE * 32) {
            int row = gtid >> 5;
            int c   = gtid & 31;
            g_w12[gtid] = (c < 16) ? w1l2[row * 16 + c] : w2l2[row * 16 + (c - 16)];
        }
    }

    for (int idx = threadIdx.x; idx < IN_DIM * L1_DIM; idx += 256) {
        int k = idx >> 4;
        int j = idx & 15;
        sw[j * IN_DIM + k]             = w1[idx];
        sw[WS_STRIDE + j * IN_DIM + k] = w2[idx];
    }
    __syncthreads();

    int node = blockIdx.x * 128 + (threadIdx.x >> 1);
    int m    = threadIdx.x & 1;
    if (node >= N_NODES) return;

    const ulonglong2* zr  = (const ulonglong2*)(z + (size_t)node * IN_DIM);
    const ulonglong2* wsr = (const ulonglong2*)(sw + m * WS_STRIDE);

    unsigned long long acc[16];
#pragma unroll
    for (int j = 0; j < 16; j++) acc[j] = 0ull;   // packed (0.f, 0.f)

#pragma unroll 4
    for (int k4 = 0; k4 < IN_DIM / 4; k4++) {
        ulonglong2 zq = zr[k4];
#pragma unroll
        for (int j = 0; j < 16; j++) {
            ulonglong2 wq = wsr[j * (IN_DIM / 4) + k4];
            acc[j] = ffma2(zq.x, wq.x, acc[j]);
            acc[j] = ffma2(zq.y, wq.y, acc[j]);
        }
    }

    float* dst = (m == 0 ? g_h1 : g_h2) + (size_t)node * L1_DIM;
    float4* d4 = (float4*)dst;
#pragma unroll
    for (int q = 0; q < 4; q++) {
        float4 v;
        v.x = fmaxf(f2_sum(acc[4 * q + 0]), 0.f);
        v.y = fmaxf(f2_sum(acc[4 * q + 1]), 0.f);
        v.z = fmaxf(f2_sum(acc[4 * q + 2]), 0.f);
        v.w = fmaxf(f2_sum(acc[4 * q + 3]), 0.f);
        d4[q] = v;
    }
}

// ---------------------------------------------------------------------------
// Per-edge: out[e] = sigmoid( dot(h1[src], w1_l2[ty]) + dot(h2[dst], w2_l2[ty]) )
//
// Cooperative gather: 8 lanes per edge, 4 edges per warp. Lane sub = lane&7:
//   w-load: lane reads w12[ty][4*sub : 4*sub+4]   (warp touches 4 lines)
//   h-load: sub<4  -> h1[src][4*sub     : +4]
//           sub>=4 -> h2[dst][4*(sub-4) : +4]      (warp touches 8 lines)
// The w row layout makes operand pairing position-exact, so each lane does a
// 4-wide dot and a 3-step shfl.bfly reduces the 8 partials.
// Lines/edge = 3 (vs 16 for the one-thread-per-edge version) -> L1tex
// wavefronts drop ~4x.
// ---------------------------------------------------------------------------
__global__ __launch_bounds__(256) void edge_kernel(
    const void*  __restrict__ ei,
    const void*  __restrict__ et,
    float*       __restrict__ out)
{
    int t    = blockIdx.x * 256 + threadIdx.x;
    int lane = t & 31;
    int e    = (t >> 5) * 4 + (lane >> 3);   // grid is exact: no bounds check

    int src, dst, ty;
    if (g_is64) {
        const long long* p = (const long long*)ei;
        src = (int)p[e];
        dst = (int)p[N_EDGES + e];
        ty  = (int)((const long long*)et)[e];
    } else {
        const int* p = (const int*)ei;
        src = p[e];
        dst = p[N_EDGES + e];
        ty  = ((const int*)et)[e];
    }

    int sub = lane & 7;

    float4 wv = ((const float4*)(g_w12 + (size_t)ty * 32))[sub];
    const float* hbase = (sub < 4) ? (g_h1 + (size_t)src * L1_DIM)
                                   : (g_h2 + (size_t)dst * L1_DIM);
    float4 hv = ((const float4*)hbase)[lane & 3];

    float s = hv.x * wv.x;
    s = fmaf(hv.y, wv.y, s);
    s = fmaf(hv.z, wv.z, s);
    s = fmaf(hv.w, wv.w, s);

    s += __shfl_xor_sync(0xffffffffu, s, 1);
    s += __shfl_xor_sync(0xffffffffu, s, 2);
    s += __shfl_xor_sync(0xffffffffu, s, 4);

    if (sub == 0)
        out[e] = __fdividef(1.0f, 1.0f + __expf(-s));
}

// ---------------------------------------------------------------------------
// Launch. Input order (setup_inputs dict):
//   0:z 1:edge_index 2:edge_type 3:w1_l1 4:w1_l2 5:w2_l1 6:w2_l2
// ---------------------------------------------------------------------------
extern "C" void kernel_launch(void* const* d_in, const int* in_sizes, int n_in,
                              void* d_out, int out_size) {
    const float* z    = (const float*)d_in[0];
    const void*  ei   = d_in[1];
    const void*  et   = d_in[2];
    const float* w1l1 = (const float*)d_in[3];
    const float* w1l2 = (const float*)d_in[4];
    const float* w2l1 = (const float*)d_in[5];
    const float* w2l2 = (const float*)d_in[6];
    float* out = (float*)d_out;

    node_mlp_kernel<<<(N_NODES + 127) / 128, 256>>>(
        z, w1l1, w2l1, w1l2, w2l2, (const unsigned int*)ei);
    // 8 lanes/edge, 4 edges/warp, 32 edges/block -> exact grid.
    edge_kernel<<<N_EDGES / 32, 256>>>(ei, et, out);
}

// round 15
// speedup vs baseline: 1.6729x; 1.2878x over previous
#include <cuda_runtime.h>

#define N_NODES 50000
#define N_EDGES 1000000
#define IN_DIM  256
#define N_ETYPE 1000
#define L1_DIM  16

// Scratch: per-node MLP outputs (relu(z@w1_l1), relu(z@w2_l1)), 3.2 MB each.
__device__ __align__(16) float g_h1[N_NODES * L1_DIM];
__device__ __align__(16) float g_h2[N_NODES * L1_DIM];
// Merged L2-layer weights: w12[ty][0:16) = w1_l2[ty], w12[ty][16:32) = w2_l2[ty].
__device__ __align__(128) float g_w12[N_ETYPE * 32];
// Index-dtype flag: 1 if edge_index/edge_type are int64, 0 if int32.
__device__ int g_is64;

// ---------------------------------------------------------------------------
// Packed f32x2 helpers (Blackwell FFMA2 path, PTX-only)
// ---------------------------------------------------------------------------
__device__ __forceinline__ unsigned long long ffma2(unsigned long long a,
                                                    unsigned long long b,
                                                    unsigned long long c) {
    unsigned long long d;
    asm("fma.rn.f32x2 %0, %1, %2, %3;" : "=l"(d) : "l"(a), "l"(b), "l"(c));
    return d;
}
__device__ __forceinline__ unsigned long long addf2(unsigned long long a,
                                                    unsigned long long b) {
    unsigned long long d;
    asm("add.rn.f32x2 %0, %1, %2;" : "=l"(d) : "l"(a), "l"(b));
    return d;
}
__device__ __forceinline__ float f2_sum(unsigned long long a) {
    unsigned int lo, hi;
    asm("mov.b64 {%0, %1}, %2;" : "=r"(lo), "=r"(hi) : "l"(a));
    return __uint_as_float(lo) + __uint_as_float(hi);
}

// ---------------------------------------------------------------------------
// Node MLP: h1[n] = relu(z[n] @ w1_l1), h2[n] = relu(z[n] @ w2_l1).
//
// Block: 128 threads, 128 nodes. Thread t: m = t&1 (matrix), p = t>>1,
// computes nodes {base+p, base+p+64} for matrix m. K chunked by 64:
//   zt[k4][node] transposed tile (float4 entries, +1 pad per row) ->
//     staging LDG coalesced, compute LDS conflict-free (lanes consecutive).
//   sw[m][j][k] chunk staged per iteration (keeps static smem < 48 KB).
// Inner loop: 4 FFMA2 per weight LDS (2 nodes x f32x2-over-k).
// Also folds in: (a) int64-vs-int32 index detection, (b) merged w12 build.
// ---------------------------------------------------------------------------
#define CHUNK_K   64
#define K4_CHUNK  16     // float4 groups per chunk
#define ZT_STRIDE 129    // float4 entries per k4-row (128 nodes + 1 pad)
#define SW_STRIDE 68     // floats per j-row (64 + 4 pad)

__global__ __launch_bounds__(128) void node_mlp_kernel(
    const float* __restrict__ z,
    const float* __restrict__ w1,     // [256][16] row-major
    const float* __restrict__ w2,     // [256][16] row-major
    const float* __restrict__ w1l2,   // [1000][16]
    const float* __restrict__ w2l2,   // [1000][16]
    const unsigned int* __restrict__ ei_words)
{
    __shared__ __align__(16) float4 zt[K4_CHUNK * ZT_STRIDE];    // 33024 B
    __shared__ __align__(16) float  sw[2 * 16 * SW_STRIDE];      //  8704 B

    int t = threadIdx.x;

    // (a) dtype detection: edge values < 50000 => int64 iff high words all 0.
    if (blockIdx.x == 0 && t < 32) {
        unsigned int v = ei_words[2 * t + 1];
        unsigned int b = __ballot_sync(0xffffffffu, v == 0u);
        if (t == 0) g_is64 = (b == 0xffffffffu) ? 1 : 0;
    }
    // (b) merged w12 table: 1000 rows x 32 floats.
    {
        int gtid = blockIdx.x * 128 + t;
        if (gtid < N_ETYPE * 32) {
            int row = gtid >> 5;
            int c   = gtid & 31;
            g_w12[gtid] = (c < 16) ? w1l2[row * 16 + c] : w2l2[row * 16 + (c - 16)];
        }
    }

    int m    = t & 1;
    int p    = t >> 1;
    int base = blockIdx.x * 128;

    unsigned long long acc0[16], acc1[16];
#pragma unroll
    for (int j = 0; j < 16; j++) { acc0[j] = 0ull; acc1[j] = 0ull; }

    const ulonglong2* ztu = (const ulonglong2*)zt;

    for (int c = 0; c < IN_DIM / CHUNK_K; c++) {
        __syncthreads();   // previous chunk fully consumed

        // Stage z chunk transposed: 2048 float4 entries, 16 per thread.
#pragma unroll
        for (int i = 0; i < 16; i++) {
            int flat = i * 128 + t;
            int k4   = flat & 15;
            int n    = flat >> 4;
            int row  = base + n;
            if (row >= N_NODES) row = N_NODES - 1;   // clamp (last block)
            zt[k4 * ZT_STRIDE + n] =
                ((const float4*)(z + (size_t)row * IN_DIM + c * CHUNK_K))[k4];
        }
        // Stage weight chunk transposed: 1024 floats per matrix.
#pragma unroll
        for (int i = 0; i < 8; i++) {
            int flat = i * 128 + t;
            int kl   = flat >> 4;
            int j    = flat & 15;
            int gk   = c * CHUNK_K + kl;
            sw[j * SW_STRIDE + kl]                  = w1[gk * 16 + j];
            sw[(16 + j) * SW_STRIDE + kl]           = w2[gk * 16 + j];
        }
        __syncthreads();

        const float* swm = sw + m * 16 * SW_STRIDE;
#pragma unroll 2
        for (int k4 = 0; k4 < K4_CHUNK; k4++) {
            ulonglong2 zq0 = ztu[k4 * ZT_STRIDE + p];
            ulonglong2 zq1 = ztu[k4 * ZT_STRIDE + p + 64];
#pragma unroll
            for (int j = 0; j < 16; j++) {
                ulonglong2 wq = *(const ulonglong2*)(swm + j * SW_STRIDE + k4 * 4);
                acc0[j] = ffma2(zq0.x, wq.x, acc0[j]);
                acc0[j] = ffma2(zq0.y, wq.y, acc0[j]);
                acc1[j] = ffma2(zq1.x, wq.x, acc1[j]);
                acc1[j] = ffma2(zq1.y, wq.y, acc1[j]);
            }
        }
    }

    float* htab = (m == 0) ? g_h1 : g_h2;
    int node0 = base + p;          // always < N_NODES (max 49983)
    int node1 = base + p + 64;
    {
        float4* d4 = (float4*)(htab + (size_t)node0 * L1_DIM);
#pragma unroll
        for (int q = 0; q < 4; q++) {
            float4 v;
            v.x = fmaxf(f2_sum(acc0[4 * q + 0]), 0.f);
            v.y = fmaxf(f2_sum(acc0[4 * q + 1]), 0.f);
            v.z = fmaxf(f2_sum(acc0[4 * q + 2]), 0.f);
            v.w = fmaxf(f2_sum(acc0[4 * q + 3]), 0.f);
            d4[q] = v;
        }
    }
    if (node1 < N_NODES) {
        float4* d4 = (float4*)(htab + (size_t)node1 * L1_DIM);
#pragma unroll
        for (int q = 0; q < 4; q++) {
            float4 v;
            v.x = fmaxf(f2_sum(acc1[4 * q + 0]), 0.f);
            v.y = fmaxf(f2_sum(acc1[4 * q + 1]), 0.f);
            v.z = fmaxf(f2_sum(acc1[4 * q + 2]), 0.f);
            v.w = fmaxf(f2_sum(acc1[4 * q + 3]), 0.f);
            d4[q] = v;
        }
    }
}

// ---------------------------------------------------------------------------
// Edge kernel: out[e] = sigmoid(dot(h1[src],w1_l2[ty]) + dot(h2[dst],w2_l2[ty]))
//
// 8 lanes per edge-PAIR group; each group handles edges (e0, e0+1):
//   - index loads vectorized (pairs adjacent): 3 loads, issued up front
//   - 4 independent LDG.128 gathers (w0, w1, h0, h1) -> 2x MLP vs R2
//   - both dots reduced together: pack (s0,s1) as 64-bit, 3x shfl.bfly +
//     add.rn.f32x2, sub==0 stores float2.
// ---------------------------------------------------------------------------
__global__ __launch_bounds__(256) void edge_kernel(
    const void*  __restrict__ ei,
    const void*  __restrict__ et,
    float*       __restrict__ out)
{
    int t    = blockIdx.x * 256 + threadIdx.x;
    int lane = threadIdx.x & 31;
    int g    = lane >> 3;
    int sub  = lane & 7;
    int e0   = (t >> 5) * 8 + g * 2;   // exact grid: no bounds check

    int src0, src1, dst0, dst1, ty0, ty1;
    if (g_is64) {
        longlong2 s = *(const longlong2*)((const long long*)ei + e0);
        longlong2 d = *(const longlong2*)((const long long*)ei + N_EDGES + e0);
        longlong2 y = *(const longlong2*)((const long long*)et + e0);
        src0 = (int)s.x; src1 = (int)s.y;
        dst0 = (int)d.x; dst1 = (int)d.y;
        ty0  = (int)y.x; ty1  = (int)y.y;
    } else {
        int2 s = *(const int2*)((const int*)ei + e0);
        int2 d = *(const int2*)((const int*)ei + N_EDGES + e0);
        int2 y = *(const int2*)((const int*)et + e0);
        src0 = s.x; src1 = s.y;
        dst0 = d.x; dst1 = d.y;
        ty0  = y.x; ty1  = y.y;
    }

    float4 wv0 = ((const float4*)(g_w12 + (size_t)ty0 * 32))[sub];
    float4 wv1 = ((const float4*)(g_w12 + (size_t)ty1 * 32))[sub];
    const float* hb0 = (sub < 4) ? (g_h1 + (size_t)src0 * L1_DIM)
                                 : (g_h2 + (size_t)dst0 * L1_DIM);
    const float* hb1 = (sub < 4) ? (g_h1 + (size_t)src1 * L1_DIM)
                                 : (g_h2 + (size_t)dst1 * L1_DIM);
    float4 h0 = ((const float4*)hb0)[lane & 3];
    float4 h1 = ((const float4*)hb1)[lane & 3];

    float s0 = h0.x * wv0.x;
    s0 = fmaf(h0.y, wv0.y, s0);
    s0 = fmaf(h0.z, wv0.z, s0);
    s0 = fmaf(h0.w, wv0.w, s0);
    float s1 = h1.x * wv1.x;
    s1 = fmaf(h1.y, wv1.y, s1);
    s1 = fmaf(h1.z, wv1.z, s1);
    s1 = fmaf(h1.w, wv1.w, s1);

    unsigned long long pk;
    asm("mov.b64 %0, {%1, %2};" : "=l"(pk)
        : "r"(__float_as_uint(s0)), "r"(__float_as_uint(s1)));
    pk = addf2(pk, __shfl_xor_sync(0xffffffffu, pk, 1));
    pk = addf2(pk, __shfl_xor_sync(0xffffffffu, pk, 2));
    pk = addf2(pk, __shfl_xor_sync(0xffffffffu, pk, 4));

    if (sub == 0) {
        unsigned int lo, hi;
        asm("mov.b64 {%0, %1}, %2;" : "=r"(lo), "=r"(hi) : "l"(pk));
        float2 o;
        o.x = __fdividef(1.0f, 1.0f + __expf(-__uint_as_float(lo)));
        o.y = __fdividef(1.0f, 1.0f + __expf(-__uint_as_float(hi)));
        *(float2*)(out + e0) = o;
    }
}

// ---------------------------------------------------------------------------
// Launch. Input order: 0:z 1:edge_index 2:edge_type 3:w1_l1 4:w1_l2 5:w2_l1 6:w2_l2
// ---------------------------------------------------------------------------
extern "C" void kernel_launch(void* const* d_in, const int* in_sizes, int n_in,
                              void* d_out, int out_size) {
    const float* z    = (const float*)d_in[0];
    const void*  ei   = d_in[1];
    const void*  et   = d_in[2];
    const float* w1l1 = (const float*)d_in[3];
    const float* w1l2 = (const float*)d_in[4];
    const float* w2l1 = (const float*)d_in[5];
    const float* w2l2 = (const float*)d_in[6];
    float* out = (float*)d_out;

    node_mlp_kernel<<<(N_NODES + 127) / 128, 128>>>(
        z, w1l1, w2l1, w1l2, w2l2, (const unsigned int*)ei);
    // 8 lanes per edge-pair, 8 edges/warp, 64 edges/block -> exact grid.
    edge_kernel<<<N_EDGES / 64, 256>>>(ei, et, out);
}